// round 11
// baseline (speedup 1.0000x reference)
#include <cuda_runtime.h>
#include <cstdint>

#define BATCH 2
#define SEQ   2048
#define HID   1024
#define NH    16
#define HD    64
#define QKV_O 1152            // NH*HD + 2*HD
#define ROWS  (BATCH * SEQ)   // 4096

// Scratch (allocation-free)
__device__ float g_qkv[(size_t)ROWS * QKV_O];
__device__ float g_attn[(size_t)ROWS * HID];

// ---------------------------------------------------------------------------
// TF32 / mma helpers
// ---------------------------------------------------------------------------
__device__ __forceinline__ unsigned f2t(float x) {
    unsigned u;
    asm("cvt.rna.tf32.f32 %0, %1;" : "=r"(u) : "f"(x));
    return u;
}

__device__ __forceinline__ uint4 f2t4(float4 v) {
    uint4 t;
    t.x = f2t(v.x); t.y = f2t(v.y); t.z = f2t(v.z); t.w = f2t(v.w);
    return t;
}

__device__ __forceinline__ uint4 f2t4s(float4 v, float s) {
    uint4 t;
    t.x = f2t(v.x * s); t.y = f2t(v.y * s); t.z = f2t(v.z * s); t.w = f2t(v.w * s);
    return t;
}

// D(16x8,f32) += A(16x8,tf32,row) * B(8x8,tf32,col)
// NOT volatile: pure register op, lets the compiler pipeline around ldsm/STS.
__device__ __forceinline__ void mma8(float* d, const unsigned* a, const unsigned* b) {
    asm("mma.sync.aligned.m16n8k8.row.col.f32.tf32.tf32.f32 "
        "{%0,%1,%2,%3}, {%4,%5,%6,%7}, {%8,%9}, {%0,%1,%2,%3};\n"
        : "+f"(d[0]), "+f"(d[1]), "+f"(d[2]), "+f"(d[3])
        : "r"(a[0]), "r"(a[1]), "r"(a[2]), "r"(a[3]), "r"(b[0]), "r"(b[1]));
}

// ldmatrix x4: four 8x8 b16 tiles == four 8x4 tf32 tiles, lane l -> [l/4][l%4]
__device__ __forceinline__ void ldsm4(unsigned* r, const unsigned* p) {
    unsigned addr = (unsigned)__cvta_generic_to_shared(p);
    asm volatile(
        "ldmatrix.sync.aligned.m8n8.x4.shared.b16 {%0,%1,%2,%3}, [%4];"
        : "=r"(r[0]), "=r"(r[1]), "=r"(r[2]), "=r"(r[3]) : "r"(addr));
}

// ---------------------------------------------------------------------------
// GEMM (NT): C[M,N] = A[M,K] * B[N,K]^T, tf32 tensor cores, fp32 accumulate.
// Block 128x128, BK=16, 256 threads = 8 warps (2m x 4n), warp tile 64x32.
// Double-buffered smem (stride 20). Fragments via ldmatrix.x4 (conflict-free).
// Staging via permuted conflict-free STS.128.
// ---------------------------------------------------------------------------
#define GEMM_SLAB (128 * 20)
#define GEMM_SMEM_BYTES (4 * GEMM_SLAB * 4)

__global__ void __launch_bounds__(256, 2)
gemm_nt_tc(const float* __restrict__ A, const float* __restrict__ Bm,
           float* __restrict__ C, int M, int N, int K)
{
    extern __shared__ unsigned gsm[];
    unsigned* As = gsm;                    // [2][GEMM_SLAB]
    unsigned* Bs = gsm + 2 * GEMM_SLAB;    // [2][GEMM_SLAB]

    const int tid = threadIdx.x;
    const int lane = tid & 31, warp = tid >> 5;
    const int wm = warp >> 2, wn = warp & 3;
    const int r = lane >> 2, c = lane & 3;
    const int bm = blockIdx.y, bn = blockIdx.x;

    const float* Ab = A + (size_t)bm * 128 * K;
    const float* Bb = Bm + (size_t)bn * 128 * K;

    // staging row permutation (swap bits 1<->2) for conflict-free STS.128
    const int srow_raw = tid >> 1;
    const int srow = (srow_raw & ~6) | ((srow_raw & 2) << 1) | ((srow_raw & 4) >> 1);
    const int sk = (tid & 1) * 8;       // 0 or 8

    // per-lane ldmatrix base offsets
    const unsigned* aFrag = As + (wm * 64 + (lane & 15)) * 20 + (lane >> 4) * 4;
    const unsigned* bFrag = Bs + (wn * 32 + (lane & 7)) * 20 + ((lane >> 3) & 3) * 4;

    float acc[4][4][4];
#pragma unroll
    for (int i = 0; i < 4; i++)
#pragma unroll
        for (int j = 0; j < 4; j++)
#pragma unroll
            for (int k = 0; k < 4; k++) acc[i][j][k] = 0.f;

    // stage slab 0 into buffer 0
    {
        float4 a0v = *(const float4*)(Ab + (size_t)srow * K + sk);
        float4 a1v = *(const float4*)(Ab + (size_t)srow * K + sk + 4);
        float4 b0v = *(const float4*)(Bb + (size_t)srow * K + sk);
        float4 b1v = *(const float4*)(Bb + (size_t)srow * K + sk + 4);
        *(uint4*)&As[srow * 20 + sk]     = f2t4(a0v);
        *(uint4*)&As[srow * 20 + sk + 4] = f2t4(a1v);
        *(uint4*)&Bs[srow * 20 + sk]     = f2t4(b0v);
        *(uint4*)&Bs[srow * 20 + sk + 4] = f2t4(b1v);
    }
    __syncthreads();

    const int niter = K / 16;
    int buf = 0;
    for (int it = 0; it < niter; it++) {
        const bool more = (it + 1 < niter);
        float4 a0v, a1v, b0v, b1v;
        if (more) {
            int ko = (it + 1) * 16 + sk;
            a0v = *(const float4*)(Ab + (size_t)srow * K + ko);
            a1v = *(const float4*)(Ab + (size_t)srow * K + ko + 4);
            b0v = *(const float4*)(Bb + (size_t)srow * K + ko);
            b1v = *(const float4*)(Bb + (size_t)srow * K + ko + 4);
        }

        const unsigned* aP = aFrag + buf * GEMM_SLAB;
        const unsigned* bP = bFrag + buf * GEMM_SLAB;

        // B fragments: one ldmatrix.x4 per nt covers both k-steps
        unsigned bf[4][4];
#pragma unroll
        for (int nt = 0; nt < 4; nt++)
            ldsm4(bf[nt], bP + nt * 8 * 20);

#pragma unroll
        for (int ks = 0; ks < 2; ks++) {
            unsigned af[4][4];
#pragma unroll
            for (int mt = 0; mt < 4; mt++)
                ldsm4(af[mt], aP + mt * 16 * 20 + ks * 8);
#pragma unroll
            for (int mt = 0; mt < 4; mt++)
#pragma unroll
                for (int nt = 0; nt < 4; nt++) {
                    unsigned bb[2] = {bf[nt][2 * ks], bf[nt][2 * ks + 1]};
                    mma8(acc[mt][nt], af[mt], bb);
                }
        }

        if (more) {
            unsigned* a_dst = &As[(buf ^ 1) * GEMM_SLAB + srow * 20 + sk];
            *(uint4*)(a_dst)     = f2t4(a0v);
            *(uint4*)(a_dst + 4) = f2t4(a1v);
            unsigned* b_dst = &Bs[(buf ^ 1) * GEMM_SLAB + srow * 20 + sk];
            *(uint4*)(b_dst)     = f2t4(b0v);
            *(uint4*)(b_dst + 4) = f2t4(b1v);
        }
        __syncthreads();
        buf ^= 1;
    }

    float* Cb = C + (size_t)bm * 128 * N + (size_t)bn * 128;
#pragma unroll
    for (int mt = 0; mt < 4; mt++)
#pragma unroll
        for (int nt = 0; nt < 4; nt++) {
            int row = wm * 64 + mt * 16 + r;
            int col = wn * 32 + nt * 8 + 2 * c;
            *(float2*)(Cb + (size_t)row * N + col) =
                make_float2(acc[mt][nt][0], acc[mt][nt][1]);
            *(float2*)(Cb + (size_t)(row + 8) * N + col) =
                make_float2(acc[mt][nt][2], acc[mt][nt][3]);
        }
}

// ---------------------------------------------------------------------------
// LayerNorm over the 1152-wide QKV rows, in place in g_qkv.
// ---------------------------------------------------------------------------
__global__ void __launch_bounds__(256)
ln_kernel(const float* __restrict__ gamma, const float* __restrict__ beta)
{
    const int row = blockIdx.x;
    float* p = g_qkv + (size_t)row * QKV_O;
    const int tid = threadIdx.x;

    float s = 0.f, sq = 0.f;
    for (int i = tid; i < QKV_O; i += 256) {
        float v = p[i];
        s += v;
        sq += v * v;
    }
    __shared__ float red[256], red2[256];
    red[tid] = s; red2[tid] = sq;
    __syncthreads();
    for (int off = 128; off > 0; off >>= 1) {
        if (tid < off) {
            red[tid] += red[tid + off];
            red2[tid] += red2[tid + off];
        }
        __syncthreads();
    }
    const float inv_n = 1.0f / (float)QKV_O;
    float mean = red[0] * inv_n;
    float var = red2[0] * inv_n - mean * mean;
    float rstd = rsqrtf(var + 1e-5f);

    for (int i = tid; i < QKV_O; i += 256) {
        p[i] = (p[i] - mean) * rstd * gamma[i] + beta[i];
    }
}

// ---------------------------------------------------------------------------
// Causal MQA flash attention, tf32 mma.sync, ldmatrix fragments,
// DOUBLE-BUFFERED K/V tiles -> one barrier per kt. K prefetched before the
// S-mma block (latency hidden by mmas), V prefetched after the P-store
// (keeps peak registers down). Q pre-scaled by 1/sqrt(d)*log2(e) at staging.
// Block: 128 queries x 1 head, 8 warps. KV tile 64.
// Smem: Ks[2][64][68] (j,d), VsT[2][64][68] (d,j), Ps[128][68] (Q, then P).
// ---------------------------------------------------------------------------
#define KS_STRIDE 68
#define VT_STRIDE 68
#define PS_STRIDE 68
#define TILE_WORDS (64 * KS_STRIDE)
#define SM_VT (2 * TILE_WORDS)
#define SM_PS (4 * TILE_WORDS)
#define ATT_SMEM_WORDS (SM_PS + 128 * PS_STRIDE)
#define ATT_SMEM_BYTES (ATT_SMEM_WORDS * 4)

__global__ void __launch_bounds__(256, 2)
attn_tc()
{
    extern __shared__ unsigned smu[];
    unsigned* Ks  = smu;               // 2 buffers
    unsigned* VsT = smu + SM_VT;       // 2 buffers
    unsigned* Ps  = smu + SM_PS;

    const int tid = threadIdx.x, lane = tid & 31, warp = tid >> 5;
    const int r = lane >> 2, c = lane & 3;
    const int b = blockIdx.z, h = blockIdx.y;
    const int qt = 15 - blockIdx.x;          // heavy tiles first
    const int q0 = qt * 128;
    const float* base = g_qkv + (size_t)b * SEQ * QKV_O;
    const int qoff = 2 * HD + h * HD;
    const int m0 = warp * 16;
    const float sscale = 0.125f * 1.4426950408889634f;  // 1/sqrt(64) * log2(e)

    // per-lane ldmatrix base offsets
    const unsigned* pFrag = Ps  + (m0 + (lane & 15)) * PS_STRIDE + (lane >> 4) * 4;
    const unsigned* kFrag = Ks  + (lane & 7) * KS_STRIDE + ((lane >> 3) & 3) * 4;
    const unsigned* vFrag = VsT + (lane & 7) * VT_STRIDE + ((lane >> 3) & 3) * 4;

    // staging geometry
    const int sj = tid >> 4;                 // 0..15   (K rows, step 16)
    const int sc4 = (tid & 15) << 2;         // K d-offset
    const int vj = tid & 63;                 // V row
    const int vd4 = (tid >> 6) * 4;          // V d-offset base (step 16)

    // Stage Q (tf32, pre-scaled) into Ps region
#pragma unroll
    for (int i = 0; i < 8; i++) {
        int idx = tid + i * 256;            // 2048 float4 slots
        int row = idx >> 4;
        int c4 = (idx & 15) << 2;
        float4 v = *(const float4*)(base + (size_t)(q0 + row) * QKV_O + qoff + c4);
        *(uint4*)&Ps[row * PS_STRIDE + c4] = f2t4s(v, sscale);
    }

    // Stage K/V tile 0 into buffer 0
#pragma unroll
    for (int i = 0; i < 4; i++) {
        int j = sj + i * 16;
        float4 kv = *(const float4*)(base + (size_t)j * QKV_O + sc4);
        *(uint4*)&Ks[j * KS_STRIDE + sc4] = f2t4(kv);
    }
#pragma unroll
    for (int i = 0; i < 4; i++) {
        int d4 = vd4 + i * 16;
        float4 vv = *(const float4*)(base + (size_t)vj * QKV_O + HD + d4);
        VsT[(d4 + 0) * VT_STRIDE + vj] = f2t(vv.x);
        VsT[(d4 + 1) * VT_STRIDE + vj] = f2t(vv.y);
        VsT[(d4 + 2) * VT_STRIDE + vj] = f2t(vv.z);
        VsT[(d4 + 3) * VT_STRIDE + vj] = f2t(vv.w);
    }
    __syncthreads();

    // Preload Q fragments once via ldmatrix
    unsigned qf[8][4];
#pragma unroll
    for (int kk = 0; kk < 8; kk++)
        ldsm4(qf[kk], pFrag + kk * 8);

    float o[8][4];
#pragma unroll
    for (int n = 0; n < 8; n++)
#pragma unroll
        for (int e = 0; e < 4; e++) o[n][e] = 0.f;
    float m_lo = -1e30f, m_hi = -1e30f, l_lo = 0.f, l_hi = 0.f;
    const int i_lo = q0 + m0 + r, i_hi = i_lo + 8;

    const int ktmax = 2 * qt + 1;
    for (int kt = 0; kt <= ktmax; kt++) {
        const int k0 = kt * 64;
        const int buf = kt & 1;
        const bool more = (kt < ktmax);
        const unsigned* kP = kFrag + buf * TILE_WORDS;
        const unsigned* vP = vFrag + buf * TILE_WORDS;
        const float* nb = base + (size_t)(k0 + 64) * QKV_O;  // next tile

        // Prefetch next K tile into registers (hidden by S-mma below)
        float4 pk[4];
        if (more) {
#pragma unroll
            for (int i = 0; i < 4; i++)
                pk[i] = *(const float4*)(nb + (size_t)(sj + 16 * i) * QKV_O + sc4);
        }

        // S = Q K^T : per warp 16x64
        float s[8][4];
#pragma unroll
        for (int n = 0; n < 8; n++)
#pragma unroll
            for (int e = 0; e < 4; e++) s[n][e] = 0.f;
#pragma unroll
        for (int n = 0; n < 8; n++) {
#pragma unroll
            for (int t = 0; t < 4; t++) {
                unsigned kf[4];
                ldsm4(kf, kP + n * 8 * KS_STRIDE + t * 16);
                unsigned b0[2] = {kf[0], kf[1]};
                mma8(s[n], qf[2 * t], b0);
                unsigned b1[2] = {kf[2], kf[3]};
                mma8(s[n], qf[2 * t + 1], b1);
            }
        }

        // Store prefetched K into the idle buffer
        if (more) {
            unsigned* kD = Ks + (buf ^ 1) * TILE_WORDS;
#pragma unroll
            for (int i = 0; i < 4; i++)
                *(uint4*)&kD[(sj + 16 * i) * KS_STRIDE + sc4] = f2t4(pk[i]);
        }

        // Causal mask (S already scaled via Q)
        const bool diag = (kt >= 2 * qt);
        if (diag) {
#pragma unroll
            for (int n = 0; n < 8; n++) {
                int j0 = k0 + n * 8 + 2 * c;
                if (j0     > i_lo) s[n][0] = -1e30f;
                if (j0 + 1 > i_lo) s[n][1] = -1e30f;
                if (j0     > i_hi) s[n][2] = -1e30f;
                if (j0 + 1 > i_hi) s[n][3] = -1e30f;
            }
        }

        // Online softmax (base-2, row state in quad registers)
        float mx_lo = -1e30f, mx_hi = -1e30f;
#pragma unroll
        for (int n = 0; n < 8; n++) {
            mx_lo = fmaxf(mx_lo, fmaxf(s[n][0], s[n][1]));
            mx_hi = fmaxf(mx_hi, fmaxf(s[n][2], s[n][3]));
        }
        mx_lo = fmaxf(mx_lo, __shfl_xor_sync(0xffffffffu, mx_lo, 1));
        mx_lo = fmaxf(mx_lo, __shfl_xor_sync(0xffffffffu, mx_lo, 2));
        mx_hi = fmaxf(mx_hi, __shfl_xor_sync(0xffffffffu, mx_hi, 1));
        mx_hi = fmaxf(mx_hi, __shfl_xor_sync(0xffffffffu, mx_hi, 2));

        float mn_lo = fmaxf(m_lo, mx_lo), mn_hi = fmaxf(m_hi, mx_hi);
        float al_lo = exp2f(m_lo - mn_lo), al_hi = exp2f(m_hi - mn_hi);
        m_lo = mn_lo; m_hi = mn_hi;

        float sum_lo = 0.f, sum_hi = 0.f;
#pragma unroll
        for (int n = 0; n < 8; n++) {
            s[n][0] = exp2f(s[n][0] - mn_lo);
            s[n][1] = exp2f(s[n][1] - mn_lo);
            s[n][2] = exp2f(s[n][2] - mn_hi);
            s[n][3] = exp2f(s[n][3] - mn_hi);
            sum_lo += s[n][0] + s[n][1];
            sum_hi += s[n][2] + s[n][3];
        }
        sum_lo += __shfl_xor_sync(0xffffffffu, sum_lo, 1);
        sum_lo += __shfl_xor_sync(0xffffffffu, sum_lo, 2);
        sum_hi += __shfl_xor_sync(0xffffffffu, sum_hi, 1);
        sum_hi += __shfl_xor_sync(0xffffffffu, sum_hi, 2);
        l_lo = l_lo * al_lo + sum_lo;
        l_hi = l_hi * al_hi + sum_hi;

#pragma unroll
        for (int n = 0; n < 8; n++) {
            o[n][0] *= al_lo; o[n][1] *= al_lo;
            o[n][2] *= al_hi; o[n][3] *= al_hi;
        }

        // Store P (tf32) into warp-private Ps rows
#pragma unroll
        for (int n = 0; n < 8; n++) {
            *(uint2*)&Ps[(m0 + r) * PS_STRIDE + n * 8 + 2 * c] =
                make_uint2(f2t(s[n][0]), f2t(s[n][1]));
            *(uint2*)&Ps[(m0 + r + 8) * PS_STRIDE + n * 8 + 2 * c] =
                make_uint2(f2t(s[n][2]), f2t(s[n][3]));
        }
        __syncwarp();

        // Prefetch next V tile (hidden by PV-mma below)
        float4 pv[4];
        if (more) {
#pragma unroll
            for (int i = 0; i < 4; i++)
                pv[i] = *(const float4*)(nb + (size_t)vj * QKV_O + HD + vd4 + 16 * i);
        }

        // O += P V : P frags via ldmatrix, V frags via ldmatrix on VsT
#pragma unroll
        for (int t = 0; t < 4; t++) {
            unsigned pa[4], pb[4];
            ldsm4(pa, pFrag + (2 * t) * 8);
            ldsm4(pb, pFrag + (2 * t + 1) * 8);
#pragma unroll
            for (int n = 0; n < 8; n++) {
                unsigned vf[4];
                ldsm4(vf, vP + n * 8 * VT_STRIDE + t * 16);
                unsigned b0[2] = {vf[0], vf[1]};
                mma8(o[n], pa, b0);
                unsigned b1[2] = {vf[2], vf[3]};
                mma8(o[n], pb, b1);
            }
        }

        // Store prefetched V (transposed) into the idle buffer
        if (more) {
            unsigned* vD = VsT + (buf ^ 1) * TILE_WORDS;
#pragma unroll
            for (int i = 0; i < 4; i++) {
                int d4 = vd4 + 16 * i;
                vD[(d4 + 0) * VT_STRIDE + vj] = f2t(pv[i].x);
                vD[(d4 + 1) * VT_STRIDE + vj] = f2t(pv[i].y);
                vD[(d4 + 2) * VT_STRIDE + vj] = f2t(pv[i].z);
                vD[(d4 + 3) * VT_STRIDE + vj] = f2t(pv[i].w);
            }
        }
        __syncthreads();
    }

    // Epilogue: O / l
    float inv_lo = 1.f / l_lo, inv_hi = 1.f / l_hi;
    float* out_lo = g_attn + (size_t)(b * SEQ + i_lo) * HID + h * HD;
    float* out_hi = g_attn + (size_t)(b * SEQ + i_hi) * HID + h * HD;
#pragma unroll
    for (int n = 0; n < 8; n++) {
        int col = n * 8 + 2 * c;
        *(float2*)(out_lo + col) = make_float2(o[n][0] * inv_lo, o[n][1] * inv_lo);
        *(float2*)(out_hi + col) = make_float2(o[n][2] * inv_hi, o[n][3] * inv_hi);
    }
}

// ---------------------------------------------------------------------------
extern "C" void kernel_launch(void* const* d_in, const int* in_sizes, int n_in,
                              void* d_out, int out_size)
{
    const float* x     = (const float*)d_in[0];   // (2, 2048, 1024)
    const float* Wqkv  = (const float*)d_in[1];   // (1152, 1024)
    const float* gamma = (const float*)d_in[2];   // (1152,)
    const float* beta  = (const float*)d_in[3];   // (1152,)
    const float* Wfc   = (const float*)d_in[4];   // (1024, 1024)
    float* out = (float*)d_out;                   // (2, 2048, 1024)

    void* qkv_p = nullptr;
    void* attn_p = nullptr;
    cudaGetSymbolAddress(&qkv_p, g_qkv);
    cudaGetSymbolAddress(&attn_p, g_attn);
    float* qkv = (float*)qkv_p;
    float* attn = (float*)attn_p;

    cudaFuncSetAttribute(attn_tc, cudaFuncAttributeMaxDynamicSharedMemorySize,
                         ATT_SMEM_BYTES);

    dim3 blk(256);

    // 1) QKV GEMM: g_qkv[4096,1152] = x[4096,1024] @ Wqkv[1152,1024]^T (tf32 TC)
    gemm_nt_tc<<<dim3(QKV_O / 128, ROWS / 128), blk, GEMM_SMEM_BYTES>>>(
        x, Wqkv, qkv, ROWS, QKV_O, HID);

    // 2) LayerNorm in place (fp32)
    ln_kernel<<<ROWS, blk>>>(gamma, beta);

    // 3) Causal MQA attention -> g_attn (tf32 TC, double-buffered KV)
    attn_tc<<<dim3(SEQ / 128, NH, BATCH), blk, ATT_SMEM_BYTES>>>();

    // 4) Output projection: out = g_attn @ Wfc^T (tf32 TC)
    gemm_nt_tc<<<dim3(HID / 128, ROWS / 128), blk, GEMM_SMEM_BYTES>>>(
        attn, Wfc, out, ROWS, HID, HID);
}

// round 12
// speedup vs baseline: 1.2462x; 1.2462x over previous
#include <cuda_runtime.h>
#include <cstdint>

#define BATCH 2
#define SEQ   2048
#define HID   1024
#define NH    16
#define HD    64
#define QKV_O 1152            // NH*HD + 2*HD
#define ROWS  (BATCH * SEQ)   // 4096

// Scratch (allocation-free)
__device__ float g_qkv[(size_t)ROWS * QKV_O];
__device__ float g_attn[(size_t)ROWS * HID];

// ---------------------------------------------------------------------------
// TF32 / mma helpers
// ---------------------------------------------------------------------------
__device__ __forceinline__ unsigned f2t(float x) {
    unsigned u;
    asm("cvt.rna.tf32.f32 %0, %1;" : "=r"(u) : "f"(x));
    return u;
}

__device__ __forceinline__ uint4 f2t4(float4 v) {
    uint4 t;
    t.x = f2t(v.x); t.y = f2t(v.y); t.z = f2t(v.z); t.w = f2t(v.w);
    return t;
}

__device__ __forceinline__ uint4 f2t4s(float4 v, float s) {
    uint4 t;
    t.x = f2t(v.x * s); t.y = f2t(v.y * s); t.z = f2t(v.z * s); t.w = f2t(v.w * s);
    return t;
}

// D(16x8,f32) += A(16x8,tf32,row) * B(8x8,tf32,col)  (not volatile)
__device__ __forceinline__ void mma8(float* d, const unsigned* a, const unsigned* b) {
    asm("mma.sync.aligned.m16n8k8.row.col.f32.tf32.tf32.f32 "
        "{%0,%1,%2,%3}, {%4,%5,%6,%7}, {%8,%9}, {%0,%1,%2,%3};\n"
        : "+f"(d[0]), "+f"(d[1]), "+f"(d[2]), "+f"(d[3])
        : "r"(a[0]), "r"(a[1]), "r"(a[2]), "r"(a[3]), "r"(b[0]), "r"(b[1]));
}

// ldmatrix x4: four 8x8 b16 tiles == four 8x4 tf32 tiles, lane l -> [l/4][l%4]
__device__ __forceinline__ void ldsm4(unsigned* r, const unsigned* p) {
    unsigned addr = (unsigned)__cvta_generic_to_shared(p);
    asm volatile(
        "ldmatrix.sync.aligned.m8n8.x4.shared.b16 {%0,%1,%2,%3}, [%4];"
        : "=r"(r[0]), "=r"(r[1]), "=r"(r[2]), "=r"(r[3]) : "r"(addr));
}

// ---------------------------------------------------------------------------
// GEMM (NT): C[M,N] = A[M,K] * B[N,K]^T, tf32 tensor cores, fp32 accumulate.
// Block 128x128, BK=16, 256 threads = 8 warps (2m x 4n), warp tile 64x32.
// Double-buffered smem (stride 20). Fragments via ldmatrix.x4 (conflict-free).
// Staging via permuted conflict-free STS.128.   [measured 78.6 us — unchanged]
// ---------------------------------------------------------------------------
#define GEMM_SLAB (128 * 20)
#define GEMM_SMEM_BYTES (4 * GEMM_SLAB * 4)

__global__ void __launch_bounds__(256, 2)
gemm_nt_tc(const float* __restrict__ A, const float* __restrict__ Bm,
           float* __restrict__ C, int M, int N, int K)
{
    extern __shared__ unsigned gsm[];
    unsigned* As = gsm;                    // [2][GEMM_SLAB]
    unsigned* Bs = gsm + 2 * GEMM_SLAB;    // [2][GEMM_SLAB]

    const int tid = threadIdx.x;
    const int lane = tid & 31, warp = tid >> 5;
    const int wm = warp >> 2, wn = warp & 3;
    const int r = lane >> 2, c = lane & 3;
    const int bm = blockIdx.y, bn = blockIdx.x;

    const float* Ab = A + (size_t)bm * 128 * K;
    const float* Bb = Bm + (size_t)bn * 128 * K;

    // staging row permutation (swap bits 1<->2) for conflict-free STS.128
    const int srow_raw = tid >> 1;
    const int srow = (srow_raw & ~6) | ((srow_raw & 2) << 1) | ((srow_raw & 4) >> 1);
    const int sk = (tid & 1) * 8;       // 0 or 8

    // per-lane ldmatrix base offsets
    const unsigned* aFrag = As + (wm * 64 + (lane & 15)) * 20 + (lane >> 4) * 4;
    const unsigned* bFrag = Bs + (wn * 32 + (lane & 7)) * 20 + ((lane >> 3) & 3) * 4;

    float acc[4][4][4];
#pragma unroll
    for (int i = 0; i < 4; i++)
#pragma unroll
        for (int j = 0; j < 4; j++)
#pragma unroll
            for (int k = 0; k < 4; k++) acc[i][j][k] = 0.f;

    // stage slab 0 into buffer 0
    {
        float4 a0v = *(const float4*)(Ab + (size_t)srow * K + sk);
        float4 a1v = *(const float4*)(Ab + (size_t)srow * K + sk + 4);
        float4 b0v = *(const float4*)(Bb + (size_t)srow * K + sk);
        float4 b1v = *(const float4*)(Bb + (size_t)srow * K + sk + 4);
        *(uint4*)&As[srow * 20 + sk]     = f2t4(a0v);
        *(uint4*)&As[srow * 20 + sk + 4] = f2t4(a1v);
        *(uint4*)&Bs[srow * 20 + sk]     = f2t4(b0v);
        *(uint4*)&Bs[srow * 20 + sk + 4] = f2t4(b1v);
    }
    __syncthreads();

    const int niter = K / 16;
    int buf = 0;
    for (int it = 0; it < niter; it++) {
        const bool more = (it + 1 < niter);
        float4 a0v, a1v, b0v, b1v;
        if (more) {
            int ko = (it + 1) * 16 + sk;
            a0v = *(const float4*)(Ab + (size_t)srow * K + ko);
            a1v = *(const float4*)(Ab + (size_t)srow * K + ko + 4);
            b0v = *(const float4*)(Bb + (size_t)srow * K + ko);
            b1v = *(const float4*)(Bb + (size_t)srow * K + ko + 4);
        }

        const unsigned* aP = aFrag + buf * GEMM_SLAB;
        const unsigned* bP = bFrag + buf * GEMM_SLAB;

        // B fragments: one ldmatrix.x4 per nt covers both k-steps
        unsigned bf[4][4];
#pragma unroll
        for (int nt = 0; nt < 4; nt++)
            ldsm4(bf[nt], bP + nt * 8 * 20);

#pragma unroll
        for (int ks = 0; ks < 2; ks++) {
            unsigned af[4][4];
#pragma unroll
            for (int mt = 0; mt < 4; mt++)
                ldsm4(af[mt], aP + mt * 16 * 20 + ks * 8);
#pragma unroll
            for (int mt = 0; mt < 4; mt++)
#pragma unroll
                for (int nt = 0; nt < 4; nt++) {
                    unsigned bb[2] = {bf[nt][2 * ks], bf[nt][2 * ks + 1]};
                    mma8(acc[mt][nt], af[mt], bb);
                }
        }

        if (more) {
            unsigned* a_dst = &As[(buf ^ 1) * GEMM_SLAB + srow * 20 + sk];
            *(uint4*)(a_dst)     = f2t4(a0v);
            *(uint4*)(a_dst + 4) = f2t4(a1v);
            unsigned* b_dst = &Bs[(buf ^ 1) * GEMM_SLAB + srow * 20 + sk];
            *(uint4*)(b_dst)     = f2t4(b0v);
            *(uint4*)(b_dst + 4) = f2t4(b1v);
        }
        __syncthreads();
        buf ^= 1;
    }

    float* Cb = C + (size_t)bm * 128 * N + (size_t)bn * 128;
#pragma unroll
    for (int mt = 0; mt < 4; mt++)
#pragma unroll
        for (int nt = 0; nt < 4; nt++) {
            int row = wm * 64 + mt * 16 + r;
            int col = wn * 32 + nt * 8 + 2 * c;
            *(float2*)(Cb + (size_t)row * N + col) =
                make_float2(acc[mt][nt][0], acc[mt][nt][1]);
            *(float2*)(Cb + (size_t)(row + 8) * N + col) =
                make_float2(acc[mt][nt][2], acc[mt][nt][3]);
        }
}

// ---------------------------------------------------------------------------
// LayerNorm over the 1152-wide QKV rows, in place in g_qkv.
// ---------------------------------------------------------------------------
__global__ void __launch_bounds__(256)
ln_kernel(const float* __restrict__ gamma, const float* __restrict__ beta)
{
    const int row = blockIdx.x;
    float* p = g_qkv + (size_t)row * QKV_O;
    const int tid = threadIdx.x;

    float s = 0.f, sq = 0.f;
    for (int i = tid; i < QKV_O; i += 256) {
        float v = p[i];
        s += v;
        sq += v * v;
    }
    __shared__ float red[256], red2[256];
    red[tid] = s; red2[tid] = sq;
    __syncthreads();
    for (int off = 128; off > 0; off >>= 1) {
        if (tid < off) {
            red[tid] += red[tid + off];
            red2[tid] += red2[tid + off];
        }
        __syncthreads();
    }
    const float inv_n = 1.0f / (float)QKV_O;
    float mean = red[0] * inv_n;
    float var = red2[0] * inv_n - mean * mean;
    float rstd = rsqrtf(var + 1e-5f);

    for (int i = tid; i < QKV_O; i += 256) {
        p[i] = (p[i] - mean) * rstd * gamma[i] + beta[i];
    }
}

// ---------------------------------------------------------------------------
// Causal MQA flash attention — R8 structure (measured best, ~203 us):
// tf32 mma.sync, scalar-LDS fragments, single-buffered K/V, 2 barriers/kt,
// Q fragments persistent in registers.  Micro-tweaks only: Q pre-scaled by
// 1/sqrt(d)*log2(e) at staging; base-2 softmax (exp2f).
// Smem: Ks[64][68] (j,d), Vs[64][72] (j,d), Ps[128][68] (Q staging, then P).
// ---------------------------------------------------------------------------
#define KS_STRIDE 68
#define VS_STRIDE 72
#define PS_STRIDE 68
#define SM_VS (64 * KS_STRIDE)
#define SM_PS (SM_VS + 64 * VS_STRIDE)
#define ATT_SMEM_WORDS (SM_PS + 128 * PS_STRIDE)
#define ATT_SMEM_BYTES (ATT_SMEM_WORDS * 4)

__global__ void __launch_bounds__(256, 2)
attn_tc()
{
    extern __shared__ unsigned smu[];
    unsigned* Ks = smu;
    unsigned* Vs = smu + SM_VS;
    unsigned* Ps = smu + SM_PS;

    const int tid = threadIdx.x, lane = tid & 31, warp = tid >> 5;
    const int r = lane >> 2, c = lane & 3;
    const int b = blockIdx.z, h = blockIdx.y;
    const int qt = 15 - blockIdx.x;          // heavy tiles first
    const int q0 = qt * 128;
    const float* base = g_qkv + (size_t)b * SEQ * QKV_O;
    const int qoff = 2 * HD + h * HD;
    const int m0 = warp * 16;
    const float sscale = 0.125f * 1.4426950408889634f;  // 1/sqrt(64) * log2(e)

    // Stage Q (tf32, pre-scaled) into Ps region (vector stores, conflict-free)
#pragma unroll
    for (int i = 0; i < 8; i++) {
        int idx = tid + i * 256;            // 2048 float4 slots
        int row = idx >> 4;
        int c4 = (idx & 15) << 2;
        float4 v = *(const float4*)(base + (size_t)(q0 + row) * QKV_O + qoff + c4);
        *(uint4*)&Ps[row * PS_STRIDE + c4] = f2t4s(v, sscale);
    }
    __syncthreads();

    // Preload Q fragments once (rows m0+r, m0+r+8; k = 8*kk + c, +4)
    unsigned qf[8][4];
#pragma unroll
    for (int kk = 0; kk < 8; kk++) {
        const unsigned* p = &Ps[(m0 + r) * PS_STRIDE + kk * 8 + c];
        qf[kk][0] = p[0];
        qf[kk][1] = p[8 * PS_STRIDE];
        qf[kk][2] = p[4];
        qf[kk][3] = p[8 * PS_STRIDE + 4];
    }

    float o[8][4];
#pragma unroll
    for (int n = 0; n < 8; n++)
#pragma unroll
        for (int e = 0; e < 4; e++) o[n][e] = 0.f;
    float m_lo = -1e30f, m_hi = -1e30f, l_lo = 0.f, l_hi = 0.f;
    const int i_lo = q0 + m0 + r, i_hi = i_lo + 8;

    // staging slot geometry
    const int sj = tid >> 4;                 // 0..15
    const int sc4 = (tid & 15) << 2;         // d-offset

    const int ktmax = 2 * qt + 1;
    for (int kt = 0; kt <= ktmax; kt++) {
        const int k0 = kt * 64;
        __syncthreads();                     // Ks/Vs/Ps free (prev readers done; qf read)

        // Stage K,V tiles (tf32, vector stores, conflict-free)
#pragma unroll
        for (int i = 0; i < 4; i++) {
            int j = sj + i * 16;
            const float* src = base + (size_t)(k0 + j) * QKV_O;
            float4 kv = *(const float4*)(src + sc4);
            float4 vv = *(const float4*)(src + HD + sc4);
            *(uint4*)&Ks[j * KS_STRIDE + sc4] = f2t4(kv);
            *(uint4*)&Vs[j * VS_STRIDE + sc4] = f2t4(vv);
        }
        __syncthreads();

        // S = Q K^T : per warp 16x64 (S pre-scaled via Q)
        float s[8][4];
#pragma unroll
        for (int n = 0; n < 8; n++)
#pragma unroll
            for (int e = 0; e < 4; e++) s[n][e] = 0.f;
#pragma unroll
        for (int kk = 0; kk < 8; kk++) {
#pragma unroll
            for (int n = 0; n < 8; n++) {
                const unsigned* kp = &Ks[(n * 8 + r) * KS_STRIDE + kk * 8 + c];
                unsigned bf[2] = {kp[0], kp[4]};
                mma8(s[n], qf[kk], bf);
            }
        }

        // Causal mask
        const bool diag = (kt >= 2 * qt);
        if (diag) {
#pragma unroll
            for (int n = 0; n < 8; n++) {
                int j0 = k0 + n * 8 + 2 * c;
                if (j0     > i_lo) s[n][0] = -1e30f;
                if (j0 + 1 > i_lo) s[n][1] = -1e30f;
                if (j0     > i_hi) s[n][2] = -1e30f;
                if (j0 + 1 > i_hi) s[n][3] = -1e30f;
            }
        }

        // Online softmax (base-2, row state in quad registers)
        float mx_lo = -1e30f, mx_hi = -1e30f;
#pragma unroll
        for (int n = 0; n < 8; n++) {
            mx_lo = fmaxf(mx_lo, fmaxf(s[n][0], s[n][1]));
            mx_hi = fmaxf(mx_hi, fmaxf(s[n][2], s[n][3]));
        }
        mx_lo = fmaxf(mx_lo, __shfl_xor_sync(0xffffffffu, mx_lo, 1));
        mx_lo = fmaxf(mx_lo, __shfl_xor_sync(0xffffffffu, mx_lo, 2));
        mx_hi = fmaxf(mx_hi, __shfl_xor_sync(0xffffffffu, mx_hi, 1));
        mx_hi = fmaxf(mx_hi, __shfl_xor_sync(0xffffffffu, mx_hi, 2));

        float mn_lo = fmaxf(m_lo, mx_lo), mn_hi = fmaxf(m_hi, mx_hi);
        float al_lo = exp2f(m_lo - mn_lo), al_hi = exp2f(m_hi - mn_hi);
        m_lo = mn_lo; m_hi = mn_hi;

        float sum_lo = 0.f, sum_hi = 0.f;
#pragma unroll
        for (int n = 0; n < 8; n++) {
            s[n][0] = exp2f(s[n][0] - mn_lo);
            s[n][1] = exp2f(s[n][1] - mn_lo);
            s[n][2] = exp2f(s[n][2] - mn_hi);
            s[n][3] = exp2f(s[n][3] - mn_hi);
            sum_lo += s[n][0] + s[n][1];
            sum_hi += s[n][2] + s[n][3];
        }
        sum_lo += __shfl_xor_sync(0xffffffffu, sum_lo, 1);
        sum_lo += __shfl_xor_sync(0xffffffffu, sum_lo, 2);
        sum_hi += __shfl_xor_sync(0xffffffffu, sum_hi, 1);
        sum_hi += __shfl_xor_sync(0xffffffffu, sum_hi, 2);
        l_lo = l_lo * al_lo + sum_lo;
        l_hi = l_hi * al_hi + sum_hi;

#pragma unroll
        for (int n = 0; n < 8; n++) {
            o[n][0] *= al_lo; o[n][1] *= al_lo;
            o[n][2] *= al_hi; o[n][3] *= al_hi;
        }

        // Store P (tf32) into warp-private Ps rows
#pragma unroll
        for (int n = 0; n < 8; n++) {
            *(uint2*)&Ps[(m0 + r) * PS_STRIDE + n * 8 + 2 * c] =
                make_uint2(f2t(s[n][0]), f2t(s[n][1]));
            *(uint2*)&Ps[(m0 + r + 8) * PS_STRIDE + n * 8 + 2 * c] =
                make_uint2(f2t(s[n][2]), f2t(s[n][3]));
        }
        __syncwarp();

        // O += P V
#pragma unroll
        for (int kk = 0; kk < 8; kk++) {
            const unsigned* p = &Ps[(m0 + r) * PS_STRIDE + kk * 8 + c];
            unsigned af[4];
            af[0] = p[0];
            af[1] = p[8 * PS_STRIDE];
            af[2] = p[4];
            af[3] = p[8 * PS_STRIDE + 4];
#pragma unroll
            for (int n = 0; n < 8; n++) {
                const unsigned* vp = &Vs[(kk * 8 + c) * VS_STRIDE + n * 8 + r];
                unsigned bf[2] = {vp[0], vp[4 * VS_STRIDE]};
                mma8(o[n], af, bf);
            }
        }
    }

    // Epilogue: O / l
    float inv_lo = 1.f / l_lo, inv_hi = 1.f / l_hi;
    float* out_lo = g_attn + (size_t)(b * SEQ + i_lo) * HID + h * HD;
    float* out_hi = g_attn + (size_t)(b * SEQ + i_hi) * HID + h * HD;
#pragma unroll
    for (int n = 0; n < 8; n++) {
        int col = n * 8 + 2 * c;
        *(float2*)(out_lo + col) = make_float2(o[n][0] * inv_lo, o[n][1] * inv_lo);
        *(float2*)(out_hi + col) = make_float2(o[n][2] * inv_hi, o[n][3] * inv_hi);
    }
}

// ---------------------------------------------------------------------------
extern "C" void kernel_launch(void* const* d_in, const int* in_sizes, int n_in,
                              void* d_out, int out_size)
{
    const float* x     = (const float*)d_in[0];   // (2, 2048, 1024)
    const float* Wqkv  = (const float*)d_in[1];   // (1152, 1024)
    const float* gamma = (const float*)d_in[2];   // (1152,)
    const float* beta  = (const float*)d_in[3];   // (1152,)
    const float* Wfc   = (const float*)d_in[4];   // (1024, 1024)
    float* out = (float*)d_out;                   // (2, 2048, 1024)

    void* qkv_p = nullptr;
    void* attn_p = nullptr;
    cudaGetSymbolAddress(&qkv_p, g_qkv);
    cudaGetSymbolAddress(&attn_p, g_attn);
    float* qkv = (float*)qkv_p;
    float* attn = (float*)attn_p;

    cudaFuncSetAttribute(attn_tc, cudaFuncAttributeMaxDynamicSharedMemorySize,
                         ATT_SMEM_BYTES);

    dim3 blk(256);

    // 1) QKV GEMM: g_qkv[4096,1152] = x[4096,1024] @ Wqkv[1152,1024]^T (tf32 TC)
    gemm_nt_tc<<<dim3(QKV_O / 128, ROWS / 128), blk, GEMM_SMEM_BYTES>>>(
        x, Wqkv, qkv, ROWS, QKV_O, HID);

    // 2) LayerNorm in place (fp32)
    ln_kernel<<<ROWS, blk>>>(gamma, beta);

    // 3) Causal MQA attention -> g_attn (tf32 TC, R8 structure + micro-tweaks)
    attn_tc<<<dim3(SEQ / 128, NH, BATCH), blk, ATT_SMEM_BYTES>>>();

    // 4) Output projection: out = g_attn @ Wfc^T (tf32 TC)
    gemm_nt_tc<<<dim3(HID / 128, ROWS / 128), blk, GEMM_SMEM_BYTES>>>(
        attn, Wfc, out, ROWS, HID, HID);
}